// round 8
// baseline (speedup 1.0000x reference)
#include <cuda_runtime.h>
#include <math.h>
#include <stdint.h>

// ---------------------------------------------------------------------------
// ENAS controller sampler. H=2048, NB=8, NC=8, TEMP=5, TANH_C=2.5, OP_RED=2.5
// R6: anchor projections (w_a1 + streamed w_ih) fused as extra blocks into the
// following LSTM launch (independent work, same h input) -> overlap + fewer
// launches. Slot-9 projections eliminated (never read). ~104 launches.
// ---------------------------------------------------------------------------

#define H 2048
#define G4 8192   // 4*H

// scratch layout (floats)
#define OFF_H0   0
#define OFF_H1   (OFF_H0 + H)
#define OFF_C    (OFF_H1 + H)
#define OFF_HW2  (OFF_C + H)
#define OFF_AW1  (OFF_HW2 + H)            // 10 x 2048
#define OFF_AXP  (OFF_AW1 + 10*H)         // 10 x 8192 anchor x-projections
#define OFF_EXP  (OFF_AXP + 10*G4)        // 9 x 8192 encoder x-projections
#define SCR_TOTAL (OFF_EXP + 9*G4)

__device__ __align__(16) float    g_scratch[SCR_TOTAL];
__device__ int       g_sel[64];
__device__ unsigned  g_key[2];
__device__ float     g_acc[2];   // [0]=log_prob, [1]=entropy
__device__ unsigned  g_ctr[4];   // arrival counters for last-block fusion

// ------------------------- Threefry-2x32 (20 rounds) -----------------------
__device__ __forceinline__ void tf2x32(unsigned k0, unsigned k1,
                                       unsigned x0, unsigned x1,
                                       unsigned &y0, unsigned &y1)
{
    const unsigned ks0 = k0, ks1 = k1, ks2 = k0 ^ k1 ^ 0x1BD11BDAu;
    x0 += ks0; x1 += ks1;
    const unsigned R[8] = {13u,15u,26u,6u,17u,29u,16u,24u};
    unsigned ks[3] = {ks0, ks1, ks2};
    #pragma unroll
    for (int i = 0; i < 5; i++) {
        #pragma unroll
        for (int j = 0; j < 4; j++) {
            unsigned r = R[(i & 1) * 4 + j];
            x0 += x1;
            x1 = (x1 << r) | (x1 >> (32u - r));
            x1 ^= x0;
        }
        x0 += ks[(i + 1) % 3];
        x1 += ks[(i + 2) % 3] + (unsigned)(i + 1);
    }
    y0 = x0; y1 = x1;
}

// partitionable-mode sampling: split + gumbel-argmax + log_softmax accounting
__device__ void do_sample(const float* l, int n, unsigned* key, float* acc,
                          int* sel_slot, float* arc_out)
{
    unsigned k0 = key[0], k1 = key[1];
    unsigned nk0, nk1, s0, s1;
    tf2x32(k0, k1, 0u, 0u, nk0, nk1);   // new carry key
    tf2x32(k0, k1, 0u, 1u, s0, s1);     // subkey for this draw
    key[0] = nk0; key[1] = nk1;

    int best = 0; float bz = -3.4e38f;
    for (int a = 0; a < n; a++) {
        unsigned b1, b2;
        tf2x32(s0, s1, 0u, (unsigned)a, b1, b2);
        unsigned bits = b1 ^ b2;
        float f = __uint_as_float((bits >> 9) | 0x3F800000u) - 1.0f;
        float u = (f == 0.0f) ? 1.17549435e-38f : f;
        float g = -logf(-logf(u));
        float z = l[a] + g;
        if (z > bz) { bz = z; best = a; }
    }
    float mx = l[0];
    for (int a = 1; a < n; a++) mx = fmaxf(mx, l[a]);
    float se = 0.0f;
    for (int a = 0; a < n; a++) se += expf(l[a] - mx);
    float lse = logf(se);
    acc[0] += -((l[best] - mx) - lse);
    float ent = 0.0f;
    for (int a = 0; a < n; a++) {
        float ls = (l[a] - mx) - lse;
        ent -= ls * expf(ls);
    }
    acc[1] += ent;
    *sel_slot = best;
    *arc_out = (float)best;
}

// ------------------------------ kernels ------------------------------------
__global__ void init_kernel(float* h0, float* c, float* axp01,
                            unsigned* key, float* acc, unsigned* ctr)
{
    int i = blockIdx.x * blockDim.x + threadIdx.x;
    if (i < H)        { h0[i] = 0.0f; c[i] = 0.0f; }
    if (i < 2 * G4)   axp01[i] = 0.0f;
    if (i == 0) {
        key[0] = 0u; key[1] = 42u; acc[0] = 0.0f; acc[1] = 0.0f;
        ctr[0] = 0u; ctr[1] = 0u; ctr[2] = 0u; ctr[3] = 0u;
    }
}

// encoder_xproj[e][j] = sum_k encoder_w[e,k] * w_ih[j,k]  (streams w_ih once)
__global__ void encproj_kernel(const float* __restrict__ w_ih,
                               const float* __restrict__ enc,
                               float* __restrict__ expo)
{
    int j = blockIdx.x;          // 0..8191
    int t = threadIdx.x;         // 128 threads
    const float4* w4 = (const float4*)(w_ih + (size_t)j * H);
    const float4* e4 = (const float4*)enc;
    float4 w[4];
    #pragma unroll
    for (int i = 0; i < 4; i++) w[i] = __ldcs(&w4[t + i * 128]);
    float acc[9];
    #pragma unroll
    for (int e = 0; e < 9; e++) acc[e] = 0.0f;
    #pragma unroll
    for (int i = 0; i < 4; i++) {
        int idx = t + i * 128;
        #pragma unroll
        for (int e = 0; e < 9; e++) {
            float4 v = e4[e * 512 + idx];
            acc[e] += w[i].x * v.x + w[i].y * v.y + w[i].z * v.z + w[i].w * v.w;
        }
    }
    __shared__ float sred[9][4];
    #pragma unroll
    for (int e = 0; e < 9; e++) {
        float s = acc[e];
        for (int o = 16; o > 0; o >>= 1) s += __shfl_down_sync(0xffffffffu, s, o);
        if ((t & 31) == 0) sred[e][t >> 5] = s;
    }
    __syncthreads();
    if (t < 9) {
        float s = sred[t][0] + sred[t][1] + sred[t][2] + sred[t][3];
        expo[(size_t)t * G4 + j] = s;
    }
}

// One LSTM cell step; blocks [0,H) do the 4 gate-rows of column j.
// Blocks [H, H+nproj) run independent anchor projections of the SAME h_in:
//   proj rows [0,H)      : pw1 (w_attn_1) -> pout1 (aw1 slot)
//   proj rows [H, H+G4)  : pw2 (w_ih, streamed) -> pout2 (axp slot)
// Optional fused op-sample via last-arrival ticket (w_soft != nullptr; only
// used with grid == H).
__global__ void __launch_bounds__(256)
lstm_kernel(const float* __restrict__ w_hh,
            const float* __restrict__ b_ih,
            const float* __restrict__ b_hh,
            const float* __restrict__ xproj_base,
            const int* __restrict__ sel, int sel_off,
            const float* __restrict__ h_in,
            float* __restrict__ h_out,
            float* __restrict__ c,
            // fused projection blocks (pw1==nullptr disables)
            const float* __restrict__ pw1, float* __restrict__ pout1,
            const float* __restrict__ pw2, float* __restrict__ pout2,
            // fused op-sample (w_soft==nullptr disables)
            const float* __restrict__ w_soft,
            const float* __restrict__ b_soft,
            const float* __restrict__ b_nl, int use_bias,
            int* sel_slot, float* arc_out,
            unsigned* key, float* acc, unsigned* ctr)
{
    __shared__ float4 sh4[512];
    __shared__ float sred[8];
    __shared__ unsigned s_ticket;
    int b = blockIdx.x;
    int t = threadIdx.x;     // 256 threads
    int g = t >> 6;          // sub-row 0..3
    int r = t & 63;          // lane within row

    if (b < H) {
        // ---------------- LSTM path ----------------
        int j = b;
        const float4* w4 = (const float4*)(w_hh + ((size_t)(g * H + j)) * H);
        float4 w[8];
        #pragma unroll
        for (int i = 0; i < 8; i++) w[i] = w4[r + i * 64];

        const float4* h4 = (const float4*)h_in;
        sh4[t]       = h4[t];
        sh4[t + 256] = h4[t + 256];
        __syncthreads();

        float s = 0.0f;
        #pragma unroll
        for (int i = 0; i < 8; i++) {
            float4 h = sh4[r + i * 64];
            s += w[i].x * h.x + w[i].y * h.y + w[i].z * h.z + w[i].w * h.w;
        }
        for (int o = 16; o > 0; o >>= 1) s += __shfl_down_sync(0xffffffffu, s, o);
        if ((t & 31) == 0) sred[t >> 5] = s;
        __syncthreads();
        if (t == 0) {
            const float* xp = xproj_base;
            if (sel) xp += (size_t)(*sel + sel_off) * G4;
            float gi = sred[0] + sred[1] + xp[j]       + b_ih[j]       + b_hh[j];
            float gf = sred[2] + sred[3] + xp[j +   H] + b_ih[j +   H] + b_hh[j +   H];
            float gg = sred[4] + sred[5] + xp[j + 2*H] + b_ih[j + 2*H] + b_hh[j + 2*H];
            float go = sred[6] + sred[7] + xp[j + 3*H] + b_ih[j + 3*H] + b_hh[j + 3*H];
            float si = 1.0f / (1.0f + expf(-gi));
            float sf = 1.0f / (1.0f + expf(-gf));
            float so = 1.0f / (1.0f + expf(-go));
            float cn = sf * c[j] + si * tanhf(gg);
            c[j] = cn;
            h_out[j] = so * tanhf(cn);
        }

        if (w_soft) {
            if (t == 0) {
                __threadfence();
                s_ticket = atomicAdd(ctr, 1u);
            }
            __syncthreads();
            if (s_ticket == (unsigned)(H - 1)) {
                __threadfence();
                __shared__ float slog[8];
                for (int rr = 0; rr < 8; rr++) {
                    float ss = 0.0f;
                    for (int k = t; k < H; k += 256)
                        ss += h_out[k] * w_soft[(size_t)rr * H + k];
                    for (int o = 16; o > 0; o >>= 1)
                        ss += __shfl_down_sync(0xffffffffu, ss, o);
                    if ((t & 31) == 0) sred[t >> 5] = ss;
                    __syncthreads();
                    if (t == 0) {
                        float tot = 0.0f;
                        for (int wp = 0; wp < 8; wp++) tot += sred[wp];
                        slog[rr] = tot;
                    }
                    __syncthreads();
                }
                if (t == 0) {
                    float l[8];
                    for (int rr = 0; rr < 8; rr++) {
                        float v = tanhf((slog[rr] + b_soft[rr]) / 5.0f); // *(2.5/2.5)=1
                        if (use_bias) v += b_nl[rr];
                        l[rr] = v;
                    }
                    do_sample(l, 8, key, acc, sel_slot, arc_out);
                    *ctr = 0;
                }
            }
        }
    } else {
        // ---------------- fused projection path ----------------
        int row = (b - H) * 4 + g;
        int second = (row >= H);
        const float* W = second ? pw2 : pw1;
        int lrow = second ? row - H : row;
        const float4* w4 = (const float4*)(W + (size_t)lrow * H);
        float4 w[8];
        if (second) {
            #pragma unroll
            for (int i = 0; i < 8; i++) w[i] = __ldcs(&w4[r + i * 64]);
        } else {
            #pragma unroll
            for (int i = 0; i < 8; i++) w[i] = w4[r + i * 64];
        }

        const float4* h4 = (const float4*)h_in;
        sh4[t]       = h4[t];
        sh4[t + 256] = h4[t + 256];
        __syncthreads();

        float s = 0.0f;
        #pragma unroll
        for (int i = 0; i < 8; i++) {
            float4 h = sh4[r + i * 64];
            s += w[i].x * h.x + w[i].y * h.y + w[i].z * h.z + w[i].w * h.w;
        }
        for (int o = 16; o > 0; o >>= 1) s += __shfl_down_sync(0xffffffffu, s, o);
        if ((t & 31) == 0) sred[t >> 5] = s;
        __syncthreads();
        if (t < 4) {
            int rr = (b - H) * 4 + t;
            float v = sred[2 * t] + sred[2 * t + 1];
            if (rr < H) pout1[rr] = v;
            else        pout2[rr - H] = v;
        }
    }
}

// Fused: hw2 = w_a2 @ h (4 rows/block), then last block computes attention
// logits over n anchors and samples. grid = H/4 = 512 blocks, 256 threads.
__global__ void __launch_bounds__(256)
attn_kernel(const float* __restrict__ w_a2,
            const float* __restrict__ h_in,
            float* __restrict__ hw2,
            const float* __restrict__ v_attn,
            const float* __restrict__ aw1,
            int n, int* sel_slot, float* arc_out,
            unsigned* key, float* acc, unsigned* ctr)
{
    __shared__ float4 sh4[512];
    __shared__ float sred[8];
    __shared__ unsigned s_ticket;
    int t = threadIdx.x;
    int g = t >> 6;
    int r = t & 63;
    int j = blockIdx.x * 4 + g;

    const float4* w4 = (const float4*)(w_a2 + (size_t)j * H);
    float4 w[8];
    #pragma unroll
    for (int i = 0; i < 8; i++) w[i] = w4[r + i * 64];

    const float4* h4 = (const float4*)h_in;
    sh4[t]       = h4[t];
    sh4[t + 256] = h4[t + 256];
    __syncthreads();

    float s = 0.0f;
    #pragma unroll
    for (int i = 0; i < 8; i++) {
        float4 h = sh4[r + i * 64];
        s += w[i].x * h.x + w[i].y * h.y + w[i].z * h.z + w[i].w * h.w;
    }
    for (int o = 16; o > 0; o >>= 1) s += __shfl_down_sync(0xffffffffu, s, o);
    if ((t & 31) == 0) sred[t >> 5] = s;
    __syncthreads();
    if (t < 4) hw2[blockIdx.x * 4 + t] = sred[2 * t] + sred[2 * t + 1];

    if (t == 0) {
        __threadfence();
        s_ticket = atomicAdd(ctr, 1u);
    }
    __syncthreads();
    if (s_ticket == gridDim.x - 1) {
        __threadfence();
        __shared__ float slog[10];
        for (int a = 0; a < n; a++) {
            float ss = 0.0f;
            for (int k = t; k < H; k += 256)
                ss += tanhf(aw1[(size_t)a * H + k] + hw2[k]) * v_attn[k];
            for (int o = 16; o > 0; o >>= 1)
                ss += __shfl_down_sync(0xffffffffu, ss, o);
            if ((t & 31) == 0) sred[t >> 5] = ss;
            __syncthreads();
            if (t == 0) {
                float tot = 0.0f;
                for (int wp = 0; wp < 8; wp++) tot += sred[wp];
                slog[a] = tot;
            }
            __syncthreads();
        }
        if (t == 0) {
            float l[10];
            for (int a = 0; a < n; a++) l[a] = 2.5f * tanhf(slog[a] / 5.0f);
            do_sample(l, n, key, acc, sel_slot, arc_out);
            *ctr = 0;
        }
    }
}

__global__ void final_kernel(const float* acc, float* out)
{
    out[64] = acc[0];
    out[65] = acc[1];
}

// ------------------------------- launcher ----------------------------------
extern "C" void kernel_launch(void* const* d_in, const int* in_sizes, int n_in,
                              void* d_out, int out_size)
{
    const float* enc    = (const float*)d_in[0];
    const float* w_ih   = (const float*)d_in[1];
    const float* b_ih   = (const float*)d_in[2];
    const float* w_hh   = (const float*)d_in[3];
    const float* b_hh   = (const float*)d_in[4];
    const float* w_soft = (const float*)d_in[5];
    const float* b_soft = (const float*)d_in[6];
    const float* b_nl   = (const float*)d_in[7];
    const float* w_a1   = (const float*)d_in[8];
    const float* w_a2   = (const float*)d_in[9];
    const float* v_at   = (const float*)d_in[10];
    float* out = (float*)d_out;

    float* scr = nullptr; unsigned* key = nullptr; float* acc = nullptr;
    int* sel = nullptr; unsigned* ctr = nullptr;
    cudaGetSymbolAddress((void**)&scr, g_scratch);
    cudaGetSymbolAddress((void**)&key, g_key);
    cudaGetSymbolAddress((void**)&acc, g_acc);
    cudaGetSymbolAddress((void**)&sel, g_sel);
    cudaGetSymbolAddress((void**)&ctr, g_ctr);

    float* hbuf[2] = { scr + OFF_H0, scr + OFF_H1 };
    float* c    = scr + OFF_C;
    float* hw2  = scr + OFF_HW2;
    float* aw1  = scr + OFF_AW1;
    float* axp  = scr + OFF_AXP;
    float* expo = scr + OFF_EXP;

    init_kernel<<<64, 256>>>(hbuf[0], c, axp, key, acc, ctr);
    encproj_kernel<<<G4, 128>>>(w_ih, enc, expo);

    // plain LSTM (no proj, no op-sample)
    #define LSTM_PLAIN(XP, SEL, OFFS) \
        lstm_kernel<<<H, 256>>>(w_hh, b_ih, b_hh, (XP), (SEL), (OFFS), \
            hbuf[hp], hbuf[hp ^ 1], c, \
            nullptr, nullptr, nullptr, nullptr, \
            nullptr, nullptr, nullptr, 0, nullptr, nullptr, nullptr, nullptr, nullptr); \
        hp ^= 1;

    // LSTM + fused projections of h_in (PO2 may be null -> aw1-only, 512 blocks)
    #define LSTM_PROJ(XP, SEL, OFFS, PO1, PO2, NPB) \
        lstm_kernel<<<H + (NPB), 256>>>(w_hh, b_ih, b_hh, (XP), (SEL), (OFFS), \
            hbuf[hp], hbuf[hp ^ 1], c, \
            w_a1, (PO1), w_ih, (PO2), \
            nullptr, nullptr, nullptr, 0, nullptr, nullptr, nullptr, nullptr, nullptr); \
        hp ^= 1;

    // LSTM + fused op-sample
    #define LSTM_OPS(XP, SEL, OFFS, UB, SLOT, ARC) \
        lstm_kernel<<<H, 256>>>(w_hh, b_ih, b_hh, (XP), (SEL), (OFFS), \
            hbuf[hp], hbuf[hp ^ 1], c, \
            nullptr, nullptr, nullptr, nullptr, \
            w_soft, b_soft, b_nl, (UB), (SLOT), (ARC), key, acc, ctr); \
        hp ^= 1;

    int hp = 0;   // current h buffer
    int tc = 0;   // temporal decision counter (0..63)
    for (int s = 0; s < 2; s++) {
        int ub = (s == 0) ? 1 : 0;
        // warmup w=0: plain LSTM on encoder row 0
        LSTM_PLAIN(expo, nullptr, 0);
        // warmup w=1: LSTM + proj of w0's h into aw1 slot 0 (anchor 0 is the
        // zero vector in the reference, but aw1 slot holds h@w1 of warmup h)
        LSTM_PROJ(expo, nullptr, 0, aw1 + 0 * H, nullptr, H / 4);

        for (int l = 0; l < 8; l++) {
            int n = l + 2;
            int base = s * 32 + l * 4;
            // idx decision 0 (input = encoder row 0) + fused proj of the
            // previous step's h (warmup w1 for l==0, anchor h for l>0) into
            // slot l+1. Slot 9 (would be l==8) never exists -> dead slots cut.
            if (l == 0) {
                LSTM_PROJ(expo, nullptr, 0, aw1 + (size_t)(l + 1) * H,
                          nullptr, H / 4);
            } else {
                LSTM_PROJ(expo, nullptr, 0, aw1 + (size_t)(l + 1) * H,
                          axp + (size_t)(l + 1) * G4, (H + G4) / 4);
            }
            attn_kernel<<<H / 4, 256>>>(w_a2, hbuf[hp], hw2, v_at, aw1, n,
                                        sel + tc, out + base + 0, key, acc,
                                        ctr + 1);
            int t0 = tc++;
            // idx decision 1 (input = anchors[idx0] -> precomputed xproj slot)
            LSTM_PLAIN(axp, sel + t0, 0);
            attn_kernel<<<H / 4, 256>>>(w_a2, hbuf[hp], hw2, v_at, aw1, n,
                                        sel + tc, out + base + 2, key, acc,
                                        ctr + 1);
            int t1 = tc++;
            // op decision 0 (input = anchors[idx1]); fused op-sample
            LSTM_OPS(axp, sel + t1, 0, ub, sel + tc, out + base + 1);
            int t2 = tc++;
            // op decision 1 (input = encoder[op0 + 1]); fused op-sample
            LSTM_OPS(expo, sel + t2, 1, ub, sel + tc, out + base + 3);
            int t3 = tc++;
            // anchor step (input = encoder[op1 + 1]); projections of its h are
            // fused into the NEXT launch (idx0 of layer l+1) or skipped for
            // l==7 (slot 9 is never read by either sampler).
            LSTM_PLAIN(expo, sel + t3, 1);
        }
    }
    final_kernel<<<1, 1>>>(acc, out);

    #undef LSTM_PLAIN
    #undef LSTM_PROJ
    #undef LSTM_OPS
}

// round 11
// speedup vs baseline: 1.2000x; 1.2000x over previous
#include <cuda_runtime.h>
#include <cuda_fp16.h>
#include <math.h>
#include <stdint.h>

// ---------------------------------------------------------------------------
// ENAS controller sampler. H=2048, NB=8, NC=8, TEMP=5, TANH_C=2.5, OP_RED=2.5
// R8: weights converted to fp16 once per run (graph-captured). All hot weights
// (~84MB) fit in the 126MB L2 -> recurrent steps run mostly from L2. Matvecs
// are warp-per-row with 8 front-batched LDG.128 of packed half2. Accumulation,
// state, xproj, sampling/PRNG all stay fp32.
// ---------------------------------------------------------------------------

#define H 2048
#define G4 8192   // 4*H

// scratch layout (floats)
#define OFF_H0   0
#define OFF_H1   (OFF_H0 + H)
#define OFF_C    (OFF_H1 + H)
#define OFF_HW2  (OFF_C + H)
#define OFF_AW1  (OFF_HW2 + H)            // 10 x 2048
#define OFF_AXP  (OFF_AW1 + 10*H)         // 10 x 8192 anchor x-projections
#define OFF_EXP  (OFF_AXP + 10*G4)        // 9 x 8192 encoder x-projections
#define SCR_TOTAL (OFF_EXP + 9*G4)

__device__ __align__(16) float    g_scratch[SCR_TOTAL];
__device__ int       g_sel[64];
__device__ unsigned  g_key[2];
__device__ float     g_acc[2];   // [0]=log_prob, [1]=entropy
__device__ unsigned  g_ctr[4];   // arrival counters for last-block fusion

// fp16 weight copies (static device arrays; ~84MB total)
__device__ __align__(16) __half g_whh_h[4 * H * H];
__device__ __align__(16) __half g_wih_h[4 * H * H];
__device__ __align__(16) __half g_wa1_h[H * H];
__device__ __align__(16) __half g_wa2_h[H * H];
__device__ __align__(16) __half g_wsoft_h[8 * H];

// ------------------------- Threefry-2x32 (20 rounds) -----------------------
__device__ __forceinline__ void tf2x32(unsigned k0, unsigned k1,
                                       unsigned x0, unsigned x1,
                                       unsigned &y0, unsigned &y1)
{
    const unsigned ks0 = k0, ks1 = k1, ks2 = k0 ^ k1 ^ 0x1BD11BDAu;
    x0 += ks0; x1 += ks1;
    const unsigned R[8] = {13u,15u,26u,6u,17u,29u,16u,24u};
    unsigned ks[3] = {ks0, ks1, ks2};
    #pragma unroll
    for (int i = 0; i < 5; i++) {
        #pragma unroll
        for (int j = 0; j < 4; j++) {
            unsigned r = R[(i & 1) * 4 + j];
            x0 += x1;
            x1 = (x1 << r) | (x1 >> (32u - r));
            x1 ^= x0;
        }
        x0 += ks[(i + 1) % 3];
        x1 += ks[(i + 2) % 3] + (unsigned)(i + 1);
    }
    y0 = x0; y1 = x1;
}

// partitionable-mode sampling: split + gumbel-argmax + log_softmax accounting
__device__ void do_sample(const float* l, int n, unsigned* key, float* acc,
                          int* sel_slot, float* arc_out)
{
    unsigned k0 = key[0], k1 = key[1];
    unsigned nk0, nk1, s0, s1;
    tf2x32(k0, k1, 0u, 0u, nk0, nk1);   // new carry key
    tf2x32(k0, k1, 0u, 1u, s0, s1);     // subkey for this draw
    key[0] = nk0; key[1] = nk1;

    int best = 0; float bz = -3.4e38f;
    for (int a = 0; a < n; a++) {
        unsigned b1, b2;
        tf2x32(s0, s1, 0u, (unsigned)a, b1, b2);
        unsigned bits = b1 ^ b2;
        float f = __uint_as_float((bits >> 9) | 0x3F800000u) - 1.0f;
        float u = (f == 0.0f) ? 1.17549435e-38f : f;
        float g = -logf(-logf(u));
        float z = l[a] + g;
        if (z > bz) { bz = z; best = a; }
    }
    float mx = l[0];
    for (int a = 1; a < n; a++) mx = fmaxf(mx, l[a]);
    float se = 0.0f;
    for (int a = 0; a < n; a++) se += expf(l[a] - mx);
    float lse = logf(se);
    acc[0] += -((l[best] - mx) - lse);
    float ent = 0.0f;
    for (int a = 0; a < n; a++) {
        float ls = (l[a] - mx) - lse;
        ent -= ls * expf(ls);
    }
    acc[1] += ent;
    *sel_slot = best;
    *arc_out = (float)best;
}

// ------------------------------ kernels ------------------------------------
__global__ void init_kernel(float* h0, float* c, float* axp01,
                            unsigned* key, float* acc, unsigned* ctr)
{
    int i = blockIdx.x * blockDim.x + threadIdx.x;
    if (i < H)        { h0[i] = 0.0f; c[i] = 0.0f; }
    if (i < 2 * G4)   axp01[i] = 0.0f;
    if (i == 0) {
        key[0] = 0u; key[1] = 42u; acc[0] = 0.0f; acc[1] = 0.0f;
        ctr[0] = 0u; ctr[1] = 0u; ctr[2] = 0u; ctr[3] = 0u;
    }
}

__device__ __forceinline__ void conv_seg(const float* __restrict__ s,
                                         __half* __restrict__ d,
                                         size_t n4, size_t tid, size_t stride)
{
    const float4* s4 = (const float4*)s;
    uint2* d4 = (uint2*)d;
    for (size_t i = tid; i < n4; i += stride) {
        float4 v = s4[i];
        __half2 a = __floats2half2_rn(v.x, v.y);
        __half2 b = __floats2half2_rn(v.z, v.w);
        d4[i] = make_uint2(*(unsigned*)&a, *(unsigned*)&b);
    }
}

__global__ void convert_kernel(const float* __restrict__ whh,
                               const float* __restrict__ wih,
                               const float* __restrict__ wa1,
                               const float* __restrict__ wa2,
                               const float* __restrict__ wsoft)
{
    size_t tid = (size_t)blockIdx.x * blockDim.x + threadIdx.x;
    size_t stride = (size_t)gridDim.x * blockDim.x;
    conv_seg(whh,   g_whh_h,   (size_t)4 * H * H / 4, tid, stride);
    conv_seg(wih,   g_wih_h,   (size_t)4 * H * H / 4, tid, stride);
    conv_seg(wa1,   g_wa1_h,   (size_t)H * H / 4,     tid, stride);
    conv_seg(wa2,   g_wa2_h,   (size_t)H * H / 4,     tid, stride);
    conv_seg(wsoft, g_wsoft_h, (size_t)8 * H / 4,     tid, stride);
}

// warp dot: 8 LDG.128 of packed half2 against shared fp32 h
__device__ __forceinline__ float warp_dot_h16(const __half* __restrict__ wrow,
                                              const float4* __restrict__ sh4,
                                              int lane)
{
    const uint4* w4 = (const uint4*)wrow;
    uint4 wr[8];
    #pragma unroll
    for (int i = 0; i < 8; i++) wr[i] = w4[lane + i * 32];
    float s = 0.0f;
    #pragma unroll
    for (int i = 0; i < 8; i++) {
        int idx = lane + i * 32;
        float4 ha = sh4[idx * 2];
        float4 hb = sh4[idx * 2 + 1];
        const __half2* hw = (const __half2*)&wr[i];
        float2 p0 = __half22float2(hw[0]);
        float2 p1 = __half22float2(hw[1]);
        float2 p2 = __half22float2(hw[2]);
        float2 p3 = __half22float2(hw[3]);
        s += p0.x * ha.x + p0.y * ha.y + p1.x * ha.z + p1.y * ha.w
           + p2.x * hb.x + p2.y * hb.y + p3.x * hb.z + p3.y * hb.w;
    }
    #pragma unroll
    for (int o = 16; o > 0; o >>= 1) s += __shfl_down_sync(0xffffffffu, s, o);
    return s;
}

// encoder_xproj[e][j] = sum_k enc[e,k] * w_ih[j,k]; warp-per-row, grid 1024
__global__ void __launch_bounds__(256)
encproj_kernel(const float* __restrict__ enc, float* __restrict__ expo)
{
    int t = threadIdx.x;
    int w = t >> 5, lane = t & 31;
    int j = blockIdx.x * 8 + w;          // 0..8191
    const uint4* w4 = (const uint4*)(g_wih_h + (size_t)j * H);
    uint4 wr[8];
    #pragma unroll
    for (int i = 0; i < 8; i++) wr[i] = w4[lane + i * 32];
    const float4* e4 = (const float4*)enc;
    #pragma unroll 1
    for (int e = 0; e < 9; e++) {
        float s = 0.0f;
        #pragma unroll
        for (int i = 0; i < 8; i++) {
            int idx = lane + i * 32;
            float4 ha = __ldg(&e4[e * 512 + idx * 2]);
            float4 hb = __ldg(&e4[e * 512 + idx * 2 + 1]);
            const __half2* hw = (const __half2*)&wr[i];
            float2 p0 = __half22float2(hw[0]);
            float2 p1 = __half22float2(hw[1]);
            float2 p2 = __half22float2(hw[2]);
            float2 p3 = __half22float2(hw[3]);
            s += p0.x * ha.x + p0.y * ha.y + p1.x * ha.z + p1.y * ha.w
               + p2.x * hb.x + p2.y * hb.y + p3.x * hb.z + p3.y * hb.w;
        }
        #pragma unroll
        for (int o = 16; o > 0; o >>= 1) s += __shfl_down_sync(0xffffffffu, s, o);
        if (lane == 0) expo[(size_t)e * G4 + j] = s;
    }
}

// LSTM step. Blocks [0,1024): 2 columns each, warp-per-gate-row.
// Blocks [1024, 1024+NPB): fused anchor projections of the SAME h_in:
//   proj rows [0,H)     : w_a1 -> pout1
//   proj rows [H, H+G4) : w_ih -> pout2
// Optional fused op-sample (w_soft16 != nullptr) via last-arrival ticket.
__global__ void __launch_bounds__(256)
lstm_kernel(const float* __restrict__ b_ih,
            const float* __restrict__ b_hh,
            const float* __restrict__ xproj_base,
            const int* __restrict__ sel, int sel_off,
            const float* __restrict__ h_in,
            float* __restrict__ h_out,
            float* __restrict__ c,
            float* __restrict__ pout1, float* __restrict__ pout2,
            const __half* __restrict__ w_soft16,
            const float* __restrict__ b_soft,
            const float* __restrict__ b_nl, int use_bias,
            int* sel_slot, float* arc_out,
            unsigned* key, float* acc, unsigned* ctr)
{
    __shared__ float4 sh4[512];
    __shared__ float sred[8];
    __shared__ unsigned s_ticket;
    int b = blockIdx.x;
    int t = threadIdx.x;     // 256
    int w = t >> 5, lane = t & 31;

    const float4* h4 = (const float4*)h_in;
    sh4[t]       = h4[t];
    sh4[t + 256] = h4[t + 256];
    __syncthreads();

    if (b < 1024) {
        // ---------------- LSTM path: col j = b*2 + (w>>2), gate g = w&3 -----
        int j = b * 2 + (w >> 2);
        int g = w & 3;
        float s = warp_dot_h16(g_whh_h + ((size_t)(g * H + j)) * H, sh4, lane);
        if (lane == 0) sred[w] = s;
        __syncthreads();
        if (t < 2) {
            int j2 = b * 2 + t;
            const float* xp = xproj_base;
            if (sel) xp += (size_t)(*sel + sel_off) * G4;
            float gi = sred[t * 4 + 0] + xp[j2]         + b_ih[j2]         + b_hh[j2];
            float gf = sred[t * 4 + 1] + xp[j2 +     H] + b_ih[j2 +     H] + b_hh[j2 +     H];
            float gg = sred[t * 4 + 2] + xp[j2 + 2 * H] + b_ih[j2 + 2 * H] + b_hh[j2 + 2 * H];
            float go = sred[t * 4 + 3] + xp[j2 + 3 * H] + b_ih[j2 + 3 * H] + b_hh[j2 + 3 * H];
            float si = 1.0f / (1.0f + expf(-gi));
            float sf = 1.0f / (1.0f + expf(-gf));
            float so = 1.0f / (1.0f + expf(-go));
            float cn = sf * c[j2] + si * tanhf(gg);
            c[j2] = cn;
            h_out[j2] = so * tanhf(cn);
        }
    } else {
        // ---------------- fused projection path -----------------------------
        int row = (b - 1024) * 8 + w;
        float s;
        if (row < H) s = warp_dot_h16(g_wa1_h + (size_t)row * H, sh4, lane);
        else         s = warp_dot_h16(g_wih_h + (size_t)(row - H) * H, sh4, lane);
        if (lane == 0) {
            if (row < H) pout1[row] = s;
            else         pout2[row - H] = s;
        }
    }

    if (w_soft16) {
        if (t == 0) {
            __threadfence();
            s_ticket = atomicAdd(ctr, 1u);
        }
        __syncthreads();
        if (s_ticket == gridDim.x - 1) {
            __threadfence();
            __shared__ float slog[8];
            for (int rr = 0; rr < 8; rr++) {
                float ss = 0.0f;
                for (int k = t; k < H; k += 256)
                    ss += h_out[k] * __half2float(w_soft16[(size_t)rr * H + k]);
                #pragma unroll
                for (int o = 16; o > 0; o >>= 1)
                    ss += __shfl_down_sync(0xffffffffu, ss, o);
                if ((t & 31) == 0) sred[t >> 5] = ss;
                __syncthreads();
                if (t == 0) {
                    float tot = 0.0f;
                    for (int wp = 0; wp < 8; wp++) tot += sred[wp];
                    slog[rr] = tot;
                }
                __syncthreads();
            }
            if (t == 0) {
                float l[8];
                for (int rr = 0; rr < 8; rr++) {
                    float v = tanhf((slog[rr] + b_soft[rr]) / 5.0f); // *(2.5/2.5)=1
                    if (use_bias) v += b_nl[rr];
                    l[rr] = v;
                }
                do_sample(l, 8, key, acc, sel_slot, arc_out);
                *ctr = 0;
            }
        }
    }
}

// hw2 = w_a2 @ h (warp-per-row, grid 256), then last block computes attention
// logits over n anchors and samples.
__global__ void __launch_bounds__(256)
attn_kernel(const float* __restrict__ h_in,
            float* __restrict__ hw2,
            const float* __restrict__ v_attn,
            const float* __restrict__ aw1,
            int n, int* sel_slot, float* arc_out,
            unsigned* key, float* acc, unsigned* ctr)
{
    __shared__ float4 sh4[512];
    __shared__ float sred[8];
    __shared__ unsigned s_ticket;
    int t = threadIdx.x;
    int w = t >> 5, lane = t & 31;
    int j = blockIdx.x * 8 + w;

    const float4* h4 = (const float4*)h_in;
    sh4[t]       = h4[t];
    sh4[t + 256] = h4[t + 256];
    __syncthreads();

    float s = warp_dot_h16(g_wa2_h + (size_t)j * H, sh4, lane);
    if (lane == 0) hw2[j] = s;

    if (t == 0) {
        __threadfence();
        s_ticket = atomicAdd(ctr, 1u);
    }
    __syncthreads();
    if (s_ticket == gridDim.x - 1) {
        __threadfence();
        __shared__ float slog[10];
        for (int a = 0; a < n; a++) {
            float ss = 0.0f;
            for (int k = t; k < H; k += 256)
                ss += tanhf(aw1[(size_t)a * H + k] + hw2[k]) * v_attn[k];
            #pragma unroll
            for (int o = 16; o > 0; o >>= 1)
                ss += __shfl_down_sync(0xffffffffu, ss, o);
            if ((t & 31) == 0) sred[t >> 5] = ss;
            __syncthreads();
            if (t == 0) {
                float tot = 0.0f;
                for (int wp = 0; wp < 8; wp++) tot += sred[wp];
                slog[a] = tot;
            }
            __syncthreads();
        }
        if (t == 0) {
            float l[10];
            for (int a = 0; a < n; a++) l[a] = 2.5f * tanhf(slog[a] / 5.0f);
            do_sample(l, n, key, acc, sel_slot, arc_out);
            *ctr = 0;
        }
    }
}

__global__ void final_kernel(const float* acc, float* out)
{
    out[64] = acc[0];
    out[65] = acc[1];
}

// ------------------------------- launcher ----------------------------------
extern "C" void kernel_launch(void* const* d_in, const int* in_sizes, int n_in,
                              void* d_out, int out_size)
{
    const float* enc    = (const float*)d_in[0];
    const float* w_ih   = (const float*)d_in[1];
    const float* b_ih   = (const float*)d_in[2];
    const float* w_hh   = (const float*)d_in[3];
    const float* b_hh   = (const float*)d_in[4];
    const float* w_soft = (const float*)d_in[5];
    const float* b_soft = (const float*)d_in[6];
    const float* b_nl   = (const float*)d_in[7];
    const float* w_a1   = (const float*)d_in[8];
    const float* w_a2   = (const float*)d_in[9];
    const float* v_at   = (const float*)d_in[10];
    float* out = (float*)d_out;

    float* scr = nullptr; unsigned* key = nullptr; float* acc = nullptr;
    int* sel = nullptr; unsigned* ctr = nullptr; __half* wsoft16 = nullptr;
    cudaGetSymbolAddress((void**)&scr, g_scratch);
    cudaGetSymbolAddress((void**)&key, g_key);
    cudaGetSymbolAddress((void**)&acc, g_acc);
    cudaGetSymbolAddress((void**)&sel, g_sel);
    cudaGetSymbolAddress((void**)&ctr, g_ctr);
    cudaGetSymbolAddress((void**)&wsoft16, g_wsoft_h);

    float* hbuf[2] = { scr + OFF_H0, scr + OFF_H1 };
    float* c    = scr + OFF_C;
    float* hw2  = scr + OFF_HW2;
    float* aw1  = scr + OFF_AW1;
    float* axp  = scr + OFF_AXP;
    float* expo = scr + OFF_EXP;

    init_kernel<<<64, 256>>>(hbuf[0], c, axp, key, acc, ctr);
    convert_kernel<<<2048, 256>>>(w_hh, w_ih, w_a1, w_a2, w_soft);
    encproj_kernel<<<1024, 256>>>(enc, expo);

    // plain LSTM (no proj, no op-sample)
    #define LSTM_PLAIN(XP, SEL, OFFS) \
        lstm_kernel<<<1024, 256>>>(b_ih, b_hh, (XP), (SEL), (OFFS), \
            hbuf[hp], hbuf[hp ^ 1], c, nullptr, nullptr, \
            nullptr, nullptr, nullptr, 0, nullptr, nullptr, nullptr, nullptr, nullptr); \
        hp ^= 1;

    // LSTM + fused projections of h_in
    #define LSTM_PROJ(XP, SEL, OFFS, PO1, PO2, NPB) \
        lstm_kernel<<<1024 + (NPB), 256>>>(b_ih, b_hh, (XP), (SEL), (OFFS), \
            hbuf[hp], hbuf[hp ^ 1], c, (PO1), (PO2), \
            nullptr, nullptr, nullptr, 0, nullptr, nullptr, nullptr, nullptr, nullptr); \
        hp ^= 1;

    // LSTM + fused op-sample
    #define LSTM_OPS(XP, SEL, OFFS, UB, SLOT, ARC) \
        lstm_kernel<<<1024, 256>>>(b_ih, b_hh, (XP), (SEL), (OFFS), \
            hbuf[hp], hbuf[hp ^ 1], c, nullptr, nullptr, \
            wsoft16, b_soft, b_nl, (UB), (SLOT), (ARC), key, acc, ctr); \
        hp ^= 1;

    int hp = 0;   // current h buffer
    int tc = 0;   // temporal decision counter (0..63)
    for (int s = 0; s < 2; s++) {
        int ub = (s == 0) ? 1 : 0;
        // warmup w=0: plain LSTM on encoder row 0
        LSTM_PLAIN(expo, nullptr, 0);
        // warmup w=1: LSTM + proj of w0's h into aw1 slot 0
        LSTM_PROJ(expo, nullptr, 0, aw1 + 0 * H, nullptr, 256);

        for (int l = 0; l < 8; l++) {
            int n = l + 2;
            int base = s * 32 + l * 4;
            // idx0 (input = encoder row 0) + fused proj of previous step's h
            // into slot l+1 (aw1 only for l==0; slot-9 never exists).
            if (l == 0) {
                LSTM_PROJ(expo, nullptr, 0, aw1 + (size_t)(l + 1) * H,
                          nullptr, 256);
            } else {
                LSTM_PROJ(expo, nullptr, 0, aw1 + (size_t)(l + 1) * H,
                          axp + (size_t)(l + 1) * G4, 1280);
            }
            attn_kernel<<<256, 256>>>(hbuf[hp], hw2, v_at, aw1, n,
                                      sel + tc, out + base + 0, key, acc,
                                      ctr + 1);
            int t0 = tc++;
            // idx1 (input = anchors[idx0] -> precomputed xproj slot)
            LSTM_PLAIN(axp, sel + t0, 0);
            attn_kernel<<<256, 256>>>(hbuf[hp], hw2, v_at, aw1, n,
                                      sel + tc, out + base + 2, key, acc,
                                      ctr + 1);
            int t1 = tc++;
            // op0 (input = anchors[idx1]); fused op-sample
            LSTM_OPS(axp, sel + t1, 0, ub, sel + tc, out + base + 1);
            int t2 = tc++;
            // op1 (input = encoder[op0 + 1]); fused op-sample
            LSTM_OPS(expo, sel + t2, 1, ub, sel + tc, out + base + 3);
            int t3 = tc++;
            // anchor step (input = encoder[op1 + 1]); its projections are
            // fused into the NEXT idx0 launch (or skipped for l==7).
            LSTM_PLAIN(expo, sel + t3, 1);
        }
    }
    final_kernel<<<1, 1>>>(acc, out);

    #undef LSTM_PLAIN
    #undef LSTM_PROJ
    #undef LSTM_OPS
}